// round 2
// baseline (speedup 1.0000x reference)
#include <cuda_runtime.h>
#include <math.h>

// Problem constants
#define BB 8
#define NN 4096
#define CC 768
#define HH 8
#define DD 96
#define C3 2304
#define BH (BB*HH)
#define SPLITS 8

typedef unsigned long long u64;

// Packed f32x2 helpers (sm_103a FFMA2 path)
__device__ __forceinline__ u64 pack2(float lo, float hi) {
    u64 r; asm("mov.b64 %0, {%1, %2};" : "=l"(r) : "f"(lo), "f"(hi)); return r;
}
__device__ __forceinline__ u64 fma2(u64 a, u64 b, u64 c) {
    u64 d; asm("fma.rn.f32x2 %0, %1, %2, %3;" : "=l"(d) : "l"(a), "l"(b), "l"(c)); return d;
}
__device__ __forceinline__ float2 unpack2(u64 v) {
    float2 f; asm("mov.b64 {%0, %1}, %2;" : "=f"(f.x), "=f"(f.y) : "l"(v)); return f;
}

// Scratch (device globals — allocation-free kernel_launch)
__device__ float g_q[BB*HH*DD*NN];     // [b][h][d][n]
__device__ float g_k[BB*HH*DD*NN];
__device__ float g_v[BB*HH*DD*NN];
__device__ float g_rq[BB*HH*DD];       // 1/||q_row||
__device__ float g_rk[BB*HH*DD];
__device__ float g_part[SPLITS*BH*DD*DD];
__device__ float g_attn[BH*DD*DD];
__device__ float g_yt[BB*HH*DD*NN];    // y transposed: [b][h][d][n]

// ---------------------------------------------------------------------------
// Kernel 1: qkv = x @ W_qkv, scatter-write into q/k/v [B,H,D,N]
// Tile: BM=128, BN=128, BK=16, 256 threads, 8x8 per thread via f32x2.
// ---------------------------------------------------------------------------
__global__ __launch_bounds__(256, 2) void gemm_qkv_kernel(
    const float* __restrict__ x, const float* __restrict__ w)
{
    __shared__ __align__(16) u64 As2[16][130];  // {a,a} per (kk, m)
    __shared__ __align__(16) u64 Bs2[16][66];   // {b[2n], b[2n+1]} per (kk, n2)
    const int tid = threadIdx.x;
    const int rowBase = blockIdx.y * 128;
    const int colBase = blockIdx.x * 128;
    const int tx = tid & 15;
    const int ty = tid >> 4;

    // global-load index mapping
    const int xk4 = (tid & 3) * 4;   // kk base for x float4 load
    const int xm  = tid >> 2;        // m in 0..63 (+64 second pass)
    const int wn2 = tid & 63;        // float2 column index for w
    const int wkk = tid >> 6;        // kk base 0..3 (+4 per pass)

    u64 acc[8][4];
#pragma unroll
    for (int i = 0; i < 8; i++)
#pragma unroll
        for (int j = 0; j < 4; j++) acc[i][j] = 0ull;

    for (int t = 0; t < CC / 16; t++) {
        const int k0 = t * 16;
        float4 xr[2];
        float2 wr[4];
#pragma unroll
        for (int p = 0; p < 2; p++)
            xr[p] = *(const float4*)&x[(size_t)(rowBase + xm + p * 64) * CC + k0 + xk4];
#pragma unroll
        for (int p = 0; p < 4; p++)
            wr[p] = *(const float2*)&w[(size_t)(k0 + wkk + p * 4) * C3 + colBase + wn2 * 2];

        if (t) __syncthreads();   // previous tile fully consumed
#pragma unroll
        for (int p = 0; p < 2; p++) {
            As2[xk4 + 0][xm + p * 64] = pack2(xr[p].x, xr[p].x);
            As2[xk4 + 1][xm + p * 64] = pack2(xr[p].y, xr[p].y);
            As2[xk4 + 2][xm + p * 64] = pack2(xr[p].z, xr[p].z);
            As2[xk4 + 3][xm + p * 64] = pack2(xr[p].w, xr[p].w);
        }
#pragma unroll
        for (int p = 0; p < 4; p++)
            Bs2[wkk + p * 4][wn2] = pack2(wr[p].x, wr[p].y);
        __syncthreads();

#pragma unroll
        for (int kk = 0; kk < 16; kk++) {
            u64 aa[8], bb[4];
#pragma unroll
            for (int i = 0; i < 4; i++) {
                ulonglong2 t2 = *(const ulonglong2*)&As2[kk][ty * 8 + i * 2];
                aa[2 * i] = t2.x; aa[2 * i + 1] = t2.y;
            }
            {
                ulonglong2 b0 = *(const ulonglong2*)&Bs2[kk][tx * 4];
                ulonglong2 b1 = *(const ulonglong2*)&Bs2[kk][tx * 4 + 2];
                bb[0] = b0.x; bb[1] = b0.y; bb[2] = b1.x; bb[3] = b1.y;
            }
#pragma unroll
            for (int i = 0; i < 8; i++)
#pragma unroll
                for (int j = 0; j < 4; j++)
                    acc[i][j] = fma2(aa[i], bb[j], acc[i][j]);
        }
    }

    // Scatter: col c -> (h = c/288, d = (c%288)/3, s = c%3)
#pragma unroll
    for (int i = 0; i < 8; i++) {
        int r = rowBase + ty * 8 + i;
        int b = r >> 12;
        int n = r & 4095;
#pragma unroll
        for (int j = 0; j < 4; j++) {
            float2 v = unpack2(acc[i][j]);
            int col0 = colBase + tx * 8 + 2 * j;
#pragma unroll
            for (int half = 0; half < 2; half++) {
                int col = col0 + half;
                float val = half ? v.y : v.x;
                int h   = col / 288;
                int rem = col - h * 288;
                int d   = rem / 3;
                int s   = rem - d * 3;
                float* dst = (s == 0) ? g_q : (s == 1) ? g_k : g_v;
                dst[((b * HH + h) * DD + d) * NN + n] = val;
            }
        }
    }
}

// ---------------------------------------------------------------------------
// Kernel 2: per-(b,h,d) inverse L2 norm over N for q (y=0) and k (y=1)
// ---------------------------------------------------------------------------
__global__ __launch_bounds__(256) void norm_kernel()
{
    const int row = blockIdx.x;
    const float* src = (blockIdx.y == 0) ? g_q : g_k;
    float*       dst = (blockIdx.y == 0) ? g_rq : g_rk;
    const float* p = src + (size_t)row * NN;
    float s = 0.f;
    for (int i = threadIdx.x; i < NN; i += 256) {
        float v = p[i];
        s = fmaf(v, v, s);
    }
#pragma unroll
    for (int off = 16; off; off >>= 1) s += __shfl_down_sync(0xffffffffu, s, off);
    __shared__ float ws[8];
    if ((threadIdx.x & 31) == 0) ws[threadIdx.x >> 5] = s;
    __syncthreads();
    if (threadIdx.x < 8) {
        float t = ws[threadIdx.x];
#pragma unroll
        for (int off = 4; off; off >>= 1) t += __shfl_down_sync(0xffu, t, off);
        if (threadIdx.x == 0) dst[row] = rsqrtf(t);
    }
}

// ---------------------------------------------------------------------------
// Kernel 3: cross-covariance partials: part[sp][bh][d][e] = sum_n q[d,n]k[e,n]
// f32x2 along e. 96x96 out, 256 threads, 6x6 per thread, BK=32.
// ---------------------------------------------------------------------------
__global__ __launch_bounds__(256) void attn_part_kernel()
{
    __shared__ __align__(16) u64 Qs2[32][98];   // {q,q} [n'][d]
    __shared__ __align__(16) u64 Ks2[32][50];   // {k[2e],k[2e+1]} [n'][e2]
    const int tid = threadIdx.x;
    const int bh = blockIdx.x;
    const int n0 = blockIdx.y * (NN / SPLITS);
    const float* qp = g_q + (size_t)bh * DD * NN;
    const float* kp = g_k + (size_t)bh * DD * NN;
    const int tx = tid & 15;
    const int ty = tid >> 4;

    u64 acc[6][3];
#pragma unroll
    for (int i = 0; i < 6; i++)
#pragma unroll
        for (int j = 0; j < 3; j++) acc[i][j] = 0ull;

    for (int nc = 0; nc < NN / SPLITS; nc += 32) {
#pragma unroll
        for (int p = 0; p < 12; p++) {          // Q: 96 d x 32 n
            int idx = p * 256 + tid;
            int nn2 = idx & 31, d = idx >> 5;
            float v = qp[d * NN + n0 + nc + nn2];
            Qs2[nn2][d] = pack2(v, v);
        }
#pragma unroll
        for (int p = 0; p < 6; p++) {           // K: 48 e-pairs x 32 n
            int idx = p * 256 + tid;
            int nn2 = idx & 31, e2 = idx >> 5;
            float v0 = kp[(2 * e2)     * NN + n0 + nc + nn2];
            float v1 = kp[(2 * e2 + 1) * NN + n0 + nc + nn2];
            Ks2[nn2][e2] = pack2(v0, v1);
        }
        __syncthreads();
#pragma unroll
        for (int kk = 0; kk < 32; kk++) {
            u64 fq[6], fk[3];
#pragma unroll
            for (int i = 0; i < 3; i++) {
                ulonglong2 t2 = *(const ulonglong2*)&Qs2[kk][ty * 6 + 2 * i];
                fq[2 * i] = t2.x; fq[2 * i + 1] = t2.y;
            }
#pragma unroll
            for (int j = 0; j < 3; j++) fk[j] = Ks2[kk][tx * 3 + j];
#pragma unroll
            for (int i = 0; i < 6; i++)
#pragma unroll
                for (int j = 0; j < 3; j++)
                    acc[i][j] = fma2(fq[i], fk[j], acc[i][j]);
        }
        __syncthreads();
    }

    float* dst = g_part + ((size_t)blockIdx.y * BH + bh) * DD * DD;
#pragma unroll
    for (int i = 0; i < 6; i++)
#pragma unroll
        for (int j = 0; j < 3; j++)
            *(float2*)&dst[(ty * 6 + i) * DD + tx * 6 + 2 * j] = unpack2(acc[i][j]);
}

// ---------------------------------------------------------------------------
// Kernel 4: reduce split-K partials, apply norms * temp, softmax over e.
// ---------------------------------------------------------------------------
__global__ __launch_bounds__(128) void softmax_kernel(const float* __restrict__ temp)
{
    const int bhd = blockIdx.x;
    const int bh = bhd / DD;
    const int d  = bhd - bh * DD;
    const int h  = bh & (HH - 1);
    const int e  = threadIdx.x;

    float raw = 0.f;
    float val = -1e30f;
    if (e < DD) {
        float s = 0.f;
#pragma unroll
        for (int sp = 0; sp < SPLITS; sp++)
            s += g_part[(((size_t)sp * BH + bh) * DD + d) * DD + e];
        raw = s * g_rq[bh * DD + d] * g_rk[bh * DD + e] * temp[h];
        val = raw;
    }

    __shared__ float red[128];
    red[e] = val;
    __syncthreads();
#pragma unroll
    for (int off = 64; off >= 1; off >>= 1) {
        if (e < off) red[e] = fmaxf(red[e], red[e + off]);
        __syncthreads();
    }
    float m = red[0];
    __syncthreads();

    float ex = (e < DD) ? expf(raw - m) : 0.f;
    red[e] = ex;
    __syncthreads();
#pragma unroll
    for (int off = 64; off >= 1; off >>= 1) {
        if (e < off) red[e] += red[e + off];
        __syncthreads();
    }
    float sum = red[0];

    if (e < DD)
        g_attn[((size_t)bh * DD + d) * DD + e] = ex / sum;
}

// ---------------------------------------------------------------------------
// Kernel 5: y_t[d][n] = sum_e attn[d][e] * v[e][n]  (f32x2 along n)
// BM=96(d), BN=128(n), K=96 in chunks of 32, 256 threads, 6x8 per thread.
// ---------------------------------------------------------------------------
__global__ __launch_bounds__(256) void av_kernel()
{
    __shared__ __align__(16) u64 As2[96][33];   // {a,a} [d][e']
    __shared__ __align__(16) u64 Vs2[32][64];   // {v[2n],v[2n+1]} [e'][n2]
    const int tid = threadIdx.x;
    const int bh = blockIdx.x;
    const int n0 = blockIdx.y * 128;
    const float* ap = g_attn + (size_t)bh * DD * DD;
    const float* vp = g_v + (size_t)bh * DD * NN;
    const int tx = tid & 15;
    const int ty = tid >> 4;

    u64 acc[6][4];
#pragma unroll
    for (int i = 0; i < 6; i++)
#pragma unroll
        for (int j = 0; j < 4; j++) acc[i][j] = 0ull;

    for (int ec = 0; ec < DD; ec += 32) {
#pragma unroll
        for (int p = 0; p < 12; p++) {          // attn: 96 d x 32 e
            int idx = p * 256 + tid;
            int ee = idx & 31, d = idx >> 5;
            float v = ap[d * DD + ec + ee];
            As2[d][ee] = pack2(v, v);
        }
#pragma unroll
        for (int p = 0; p < 8; p++) {           // V: 32 e x 64 n-pairs
            int idx = p * 256 + tid;
            int n2 = idx & 63, ee = idx >> 6;
            float2 vv = *(const float2*)&vp[(size_t)(ec + ee) * NN + n0 + 2 * n2];
            Vs2[ee][n2] = pack2(vv.x, vv.y);
        }
        __syncthreads();
#pragma unroll
        for (int kk = 0; kk < 32; kk++) {
            u64 fa[6], fv[4];
#pragma unroll
            for (int i = 0; i < 6; i++) fa[i] = As2[ty * 6 + i][kk];
            {
                ulonglong2 v0 = *(const ulonglong2*)&Vs2[kk][tx * 4];
                ulonglong2 v1 = *(const ulonglong2*)&Vs2[kk][tx * 4 + 2];
                fv[0] = v0.x; fv[1] = v0.y; fv[2] = v1.x; fv[3] = v1.y;
            }
#pragma unroll
            for (int i = 0; i < 6; i++)
#pragma unroll
                for (int j = 0; j < 4; j++)
                    acc[i][j] = fma2(fa[i], fv[j], acc[i][j]);
        }
        __syncthreads();
    }

    float* yp = g_yt + (size_t)bh * DD * NN;
#pragma unroll
    for (int i = 0; i < 6; i++) {
        int d = ty * 6 + i;
#pragma unroll
        for (int j = 0; j < 4; j++)
            *(float2*)&yp[(size_t)d * NN + n0 + tx * 8 + 2 * j] = unpack2(acc[i][j]);
    }
}

// ---------------------------------------------------------------------------
// Kernel 6: out = y @ W_proj + b_proj, gathering A from g_yt [b][c'][n].
// Tile: BM=128, BN=128, BK=16, 256 threads, 8x8 per thread via f32x2.
// ---------------------------------------------------------------------------
__global__ __launch_bounds__(256, 2) void gemm_proj_kernel(
    const float* __restrict__ w, const float* __restrict__ bias,
    float* __restrict__ out)
{
    __shared__ __align__(16) u64 As2[16][130];
    __shared__ __align__(16) u64 Bs2[16][66];
    const int tid = threadIdx.x;
    const int rowBase = blockIdx.y * 128;
    const int colBase = blockIdx.x * 128;
    const int b     = rowBase >> 12;   // rows never straddle a batch (128 | 4096)
    const int nBase = rowBase & 4095;
    const int tx = tid & 15;
    const int ty = tid >> 4;

    const int am = tid & 127;          // m index for A loads
    const int ak = tid >> 7;           // kk base 0..1 (+2 per pass)
    const int wn2 = tid & 63;
    const int wkk = tid >> 6;

    u64 acc[8][4];
#pragma unroll
    for (int i = 0; i < 8; i++)
#pragma unroll
        for (int j = 0; j < 4; j++) acc[i][j] = 0ull;

    for (int t = 0; t < CC / 16; t++) {
        const int k0 = t * 16;
        float ar[8];
        float2 wr[4];
#pragma unroll
        for (int p = 0; p < 8; p++)
            ar[p] = g_yt[((size_t)b * CC + k0 + ak + 2 * p) * NN + nBase + am];
#pragma unroll
        for (int p = 0; p < 4; p++)
            wr[p] = *(const float2*)&w[(size_t)(k0 + wkk + p * 4) * CC + colBase + wn2 * 2];

        if (t) __syncthreads();
#pragma unroll
        for (int p = 0; p < 8; p++)
            As2[ak + 2 * p][am] = pack2(ar[p], ar[p]);
#pragma unroll
        for (int p = 0; p < 4; p++)
            Bs2[wkk + p * 4][wn2] = pack2(wr[p].x, wr[p].y);
        __syncthreads();

#pragma unroll
        for (int kk = 0; kk < 16; kk++) {
            u64 aa[8], bb[4];
#pragma unroll
            for (int i = 0; i < 4; i++) {
                ulonglong2 t2 = *(const ulonglong2*)&As2[kk][ty * 8 + i * 2];
                aa[2 * i] = t2.x; aa[2 * i + 1] = t2.y;
            }
            {
                ulonglong2 b0 = *(const ulonglong2*)&Bs2[kk][tx * 4];
                ulonglong2 b1 = *(const ulonglong2*)&Bs2[kk][tx * 4 + 2];
                bb[0] = b0.x; bb[1] = b0.y; bb[2] = b1.x; bb[3] = b1.y;
            }
#pragma unroll
            for (int i = 0; i < 8; i++)
#pragma unroll
                for (int j = 0; j < 4; j++)
                    acc[i][j] = fma2(aa[i], bb[j], acc[i][j]);
        }
    }

#pragma unroll
    for (int i = 0; i < 8; i++) {
        int r = rowBase + ty * 8 + i;
#pragma unroll
        for (int j = 0; j < 4; j++) {
            int col0 = colBase + tx * 8 + 2 * j;
            float2 v = unpack2(acc[i][j]);
            v.x += bias[col0];
            v.y += bias[col0 + 1];
            *(float2*)&out[(size_t)r * CC + col0] = v;
        }
    }
}

// ---------------------------------------------------------------------------
extern "C" void kernel_launch(void* const* d_in, const int* in_sizes, int n_in,
                              void* d_out, int out_size)
{
    const float* x      = (const float*)d_in[0];
    const float* w_qkv  = (const float*)d_in[1];
    const float* w_proj = (const float*)d_in[2];
    const float* b_proj = (const float*)d_in[3];
    const float* temp   = (const float*)d_in[4];
    float* out = (float*)d_out;

    gemm_qkv_kernel<<<dim3(C3 / 128, (BB * NN) / 128), 256>>>(x, w_qkv);
    norm_kernel<<<dim3(BH * DD, 2), 256>>>();
    attn_part_kernel<<<dim3(BH, SPLITS), 256>>>();
    softmax_kernel<<<BH * DD, 128>>>(temp);
    av_kernel<<<dim3(BH, NN / 128), 256>>>();
    gemm_proj_kernel<<<dim3(CC / 128, (BB * NN) / 128), 256>>>(w_proj, b_proj, out);
}

// round 3
// speedup vs baseline: 2.1321x; 2.1321x over previous
#include <cuda_runtime.h>
#include <cuda_bf16.h>
#include <math.h>

// Problem constants
#define BB 8
#define NN 4096
#define CC 768
#define HH 8
#define DD 96
#define C3 2304
#define BH (BB*HH)
#define SPLITS 8
#define K3 2304   // 3*CC, split-K depth for bf16 hi/lo GEMMs

// Scratch (device globals — allocation-free kernel_launch)
__device__ float g_q[BB*HH*DD*NN];     // [b][h][d][n]
__device__ float g_k[BB*HH*DD*NN];
__device__ float g_v[BB*HH*DD*NN];
__device__ float g_rq[BB*HH*DD];
__device__ float g_rk[BB*HH*DD];
__device__ float g_part[SPLITS*BH*DD*DD];
__device__ float g_attn[BH*DD*DD];
__device__ float g_yt[BB*HH*DD*NN];    // y transposed: [b][h][d][n]

// bf16 hi/lo split operands
__device__ __nv_bfloat16 g_xs[(size_t)BB*NN*K3];   // A' for GEMM1: [32768][2304] = [hi|lo|hi]
__device__ __nv_bfloat16 g_ws[(size_t)K3*C3];      // B' for GEMM1: [2304][2304] = [hi;hi;lo]
__device__ __nv_bfloat16 g_ys[(size_t)BB*NN*K3];   // A' for GEMM2
__device__ __nv_bfloat16 g_wps[(size_t)K3*CC];     // B' for GEMM2

// ---------------------------------------------------------------------------
// MMA / ldmatrix helpers
// ---------------------------------------------------------------------------
__device__ __forceinline__ void mma16816(float* c, const unsigned* a, const unsigned* b) {
    asm volatile(
        "mma.sync.aligned.m16n8k16.row.col.f32.bf16.bf16.f32 "
        "{%0,%1,%2,%3}, {%4,%5,%6,%7}, {%8,%9}, {%0,%1,%2,%3};"
        : "+f"(c[0]), "+f"(c[1]), "+f"(c[2]), "+f"(c[3])
        : "r"(a[0]), "r"(a[1]), "r"(a[2]), "r"(a[3]), "r"(b[0]), "r"(b[1]));
}
__device__ __forceinline__ void ldsm_x4(unsigned* r, const void* p) {
    unsigned addr = (unsigned)__cvta_generic_to_shared(p);
    asm volatile("ldmatrix.sync.aligned.m8n8.x4.shared.b16 {%0,%1,%2,%3}, [%4];"
        : "=r"(r[0]), "=r"(r[1]), "=r"(r[2]), "=r"(r[3]) : "r"(addr));
}
__device__ __forceinline__ void ldsm_x4_t(unsigned* r, const void* p) {
    unsigned addr = (unsigned)__cvta_generic_to_shared(p);
    asm volatile("ldmatrix.sync.aligned.m8n8.x4.trans.shared.b16 {%0,%1,%2,%3}, [%4];"
        : "=r"(r[0]), "=r"(r[1]), "=r"(r[2]), "=r"(r[3]) : "r"(addr));
}
__device__ __forceinline__ void split_hl(float v, __nv_bfloat16& hi, __nv_bfloat16& lo) {
    hi = __float2bfloat16(v);
    lo = __float2bfloat16(v - __bfloat162float(hi));
}

// ---------------------------------------------------------------------------
// Split kernels: fp32 -> bf16 hi/lo blocks along K
// A-side blocks: [hi | lo | hi]; B-side blocks: [hi ; hi ; lo]
// ---------------------------------------------------------------------------
__global__ __launch_bounds__(256) void split_x_kernel(const float* __restrict__ x)
{
    int idx = blockIdx.x * 256 + threadIdx.x;        // one float4 of x per thread
    int m = idx / (CC / 4);
    int k4 = (idx - m * (CC / 4)) * 4;
    float4 v = *(const float4*)&x[(size_t)m * CC + k4];
    __nv_bfloat16 hi[4], lo[4];
    split_hl(v.x, hi[0], lo[0]); split_hl(v.y, hi[1], lo[1]);
    split_hl(v.z, hi[2], lo[2]); split_hl(v.w, hi[3], lo[3]);
    __nv_bfloat16* base = g_xs + (size_t)m * K3 + k4;
    *(uint2*)(base)          = *(uint2*)hi;
    *(uint2*)(base + CC)     = *(uint2*)lo;
    *(uint2*)(base + 2 * CC) = *(uint2*)hi;
}

__global__ __launch_bounds__(256) void split_wqkv_kernel(const float* __restrict__ w)
{
    int idx = blockIdx.x * 256 + threadIdx.x;        // one float4 of w per thread
    int k = idx / (C3 / 4);
    int n4 = (idx - k * (C3 / 4)) * 4;
    float4 v = *(const float4*)&w[(size_t)k * C3 + n4];
    __nv_bfloat16 hi[4], lo[4];
    split_hl(v.x, hi[0], lo[0]); split_hl(v.y, hi[1], lo[1]);
    split_hl(v.z, hi[2], lo[2]); split_hl(v.w, hi[3], lo[3]);
    *(uint2*)&g_ws[(size_t)k * C3 + n4]              = *(uint2*)hi;
    *(uint2*)&g_ws[(size_t)(k + CC) * C3 + n4]       = *(uint2*)hi;
    *(uint2*)&g_ws[(size_t)(k + 2 * CC) * C3 + n4]   = *(uint2*)lo;
}

__global__ __launch_bounds__(256) void split_wproj_kernel(const float* __restrict__ w)
{
    int idx = blockIdx.x * 256 + threadIdx.x;
    int k = idx / (CC / 4);
    int n4 = (idx - k * (CC / 4)) * 4;
    float4 v = *(const float4*)&w[(size_t)k * CC + n4];
    __nv_bfloat16 hi[4], lo[4];
    split_hl(v.x, hi[0], lo[0]); split_hl(v.y, hi[1], lo[1]);
    split_hl(v.z, hi[2], lo[2]); split_hl(v.w, hi[3], lo[3]);
    *(uint2*)&g_wps[(size_t)k * CC + n4]             = *(uint2*)hi;
    *(uint2*)&g_wps[(size_t)(k + CC) * CC + n4]      = *(uint2*)hi;
    *(uint2*)&g_wps[(size_t)(k + 2 * CC) * CC + n4]  = *(uint2*)lo;
}

// Transpose g_yt [b][c][n] f32 -> g_ys [b*N+n][hi|lo|hi over c] bf16
__global__ __launch_bounds__(256) void ysplit_kernel()
{
    __shared__ float sm[32][33];
    const int n0 = blockIdx.x * 32;
    const int c0 = blockIdx.y * 32;
    const int b  = blockIdx.z;
    const int tx = threadIdx.x, ty = threadIdx.y;   // 32 x 8
#pragma unroll
    for (int i = 0; i < 4; i++) {
        int c = c0 + ty + i * 8;
        sm[ty + i * 8][tx] = g_yt[((size_t)b * CC + c) * NN + n0 + tx];
    }
    __syncthreads();
#pragma unroll
    for (int i = 0; i < 4; i++) {
        int n = n0 + ty + i * 8;
        int c = c0 + tx;
        float v = sm[tx][ty + i * 8];
        __nv_bfloat16 hi, lo;
        split_hl(v, hi, lo);
        __nv_bfloat16* base = g_ys + ((size_t)b * NN + n) * K3;
        base[c]          = hi;
        base[CC + c]     = lo;
        base[2 * CC + c] = hi;
    }
}

// ---------------------------------------------------------------------------
// bf16 MMA GEMM: C[M x Ncols] = A'[M x 2304] * B'[2304 x Ncols]  (fp32 accum)
// BM=128, BN=128, BK=32, 256 threads = 8 warps (4m x 2n), warp tile 32x64.
// mode 0: scatter GEMM1 output into g_q/g_k/g_v.  mode 1: out = C + bias.
// ---------------------------------------------------------------------------
__global__ __launch_bounds__(256) void mma_gemm_kernel(
    int Ncols, int mode, const float* __restrict__ bias, float* __restrict__ out)
{
    __shared__ __align__(16) __nv_bfloat16 As[128][40];   // pad 32->40: ldsm conflict-free
    __shared__ __align__(16) __nv_bfloat16 Bs[32][136];   // pad 128->136
    const __nv_bfloat16* __restrict__ A = mode ? g_ys : g_xs;
    const __nv_bfloat16* __restrict__ Bm = mode ? g_wps : g_ws;

    const int tid = threadIdx.x;
    const int wid = tid >> 5, lane = tid & 31;
    const int rowBase = blockIdx.y * 128;
    const int colBase = blockIdx.x * 128;
    const int warpM = (wid & 3) * 32;
    const int warpN = (wid >> 2) * 64;

    float acc[2][8][4];
#pragma unroll
    for (int i = 0; i < 2; i++)
#pragma unroll
        for (int j = 0; j < 8; j++)
#pragma unroll
            for (int q = 0; q < 4; q++) acc[i][j][q] = 0.f;

    // global load mapping
    const int arow = tid >> 2, acol = (tid & 3) * 8;      // A: +64 rows second pass
    const int brow = tid >> 4, bcol = (tid & 15) * 8;     // B: +16 rows second pass

    for (int t = 0; t < K3 / 32; t++) {
        const int k0 = t * 32;
        uint4 a0 = *(const uint4*)&A[(size_t)(rowBase + arow) * K3 + k0 + acol];
        uint4 a1 = *(const uint4*)&A[(size_t)(rowBase + arow + 64) * K3 + k0 + acol];
        uint4 b0 = *(const uint4*)&Bm[(size_t)(k0 + brow) * Ncols + colBase + bcol];
        uint4 b1 = *(const uint4*)&Bm[(size_t)(k0 + brow + 16) * Ncols + colBase + bcol];

        if (t) __syncthreads();
        *(uint4*)&As[arow][acol]      = a0;
        *(uint4*)&As[arow + 64][acol] = a1;
        *(uint4*)&Bs[brow][bcol]      = b0;
        *(uint4*)&Bs[brow + 16][bcol] = b1;
        __syncthreads();

#pragma unroll
        for (int ks = 0; ks < 2; ks++) {
            unsigned af[2][4];
#pragma unroll
            for (int im = 0; im < 2; im++)
                ldsm_x4(af[im], &As[warpM + im * 16 + (lane & 15)]
                                   [ks * 16 + (lane >> 4) * 8]);
            unsigned bf[8][2];
#pragma unroll
            for (int g = 0; g < 4; g++) {
                unsigned r[4];
                ldsm_x4_t(r, &Bs[ks * 16 + ((lane >> 3) & 1) * 8 + (lane & 7)]
                             [warpN + g * 16 + (lane >> 4) * 8]);
                bf[2 * g][0] = r[0]; bf[2 * g][1] = r[1];
                bf[2 * g + 1][0] = r[2]; bf[2 * g + 1][1] = r[3];
            }
#pragma unroll
            for (int im = 0; im < 2; im++)
#pragma unroll
                for (int jn = 0; jn < 8; jn++)
                    mma16816(acc[im][jn], af[im], bf[jn]);
        }
    }

    // Epilogue
#pragma unroll
    for (int im = 0; im < 2; im++) {
#pragma unroll
        for (int jn = 0; jn < 8; jn++) {
#pragma unroll
            for (int q = 0; q < 4; q++) {
                int m = warpM + im * 16 + (lane >> 2) + (q >> 1) * 8;
                int n = warpN + jn * 8 + (lane & 3) * 2 + (q & 1);
                float val = acc[im][jn][q];
                int row = rowBase + m;
                int col = colBase + n;
                if (mode == 0) {
                    int b = row >> 12;
                    int nn2 = row & 4095;
                    int h = col / 288;
                    int rem = col - h * 288;
                    int d = rem / 3;
                    int s = rem - d * 3;
                    float* dst = (s == 0) ? g_q : (s == 1) ? g_k : g_v;
                    dst[((b * HH + h) * DD + d) * NN + nn2] = val;
                } else {
                    out[(size_t)row * CC + col] = val + bias[col];
                }
            }
        }
    }
}

// ---------------------------------------------------------------------------
// Kernel: per-(b,h,d) inverse L2 norm over N for q (y=0) and k (y=1)
// ---------------------------------------------------------------------------
__global__ __launch_bounds__(256) void norm_kernel()
{
    const int row = blockIdx.x;
    const float* src = (blockIdx.y == 0) ? g_q : g_k;
    float*       dst = (blockIdx.y == 0) ? g_rq : g_rk;
    const float* p = src + (size_t)row * NN;
    float s = 0.f;
    for (int i = threadIdx.x; i < NN; i += 256) {
        float v = p[i];
        s = fmaf(v, v, s);
    }
#pragma unroll
    for (int off = 16; off; off >>= 1) s += __shfl_down_sync(0xffffffffu, s, off);
    __shared__ float ws[8];
    if ((threadIdx.x & 31) == 0) ws[threadIdx.x >> 5] = s;
    __syncthreads();
    if (threadIdx.x < 8) {
        float t = ws[threadIdx.x];
#pragma unroll
        for (int off = 4; off; off >>= 1) t += __shfl_down_sync(0xffu, t, off);
        if (threadIdx.x == 0) dst[row] = rsqrtf(t);
    }
}

// ---------------------------------------------------------------------------
// Kernel: cross-covariance partials (FFMA; small)
// ---------------------------------------------------------------------------
__global__ __launch_bounds__(256) void attn_part_kernel()
{
    __shared__ float Qs[32][97];
    __shared__ float Ks[32][97];
    const int tid = threadIdx.x;
    const int bh = blockIdx.x;
    const int n0 = blockIdx.y * (NN / SPLITS);
    const float* qp = g_q + (size_t)bh * DD * NN;
    const float* kp = g_k + (size_t)bh * DD * NN;
    const int tx = tid & 15;
    const int ty = tid >> 4;

    float acc[6][6];
#pragma unroll
    for (int i = 0; i < 6; i++)
#pragma unroll
        for (int j = 0; j < 6; j++) acc[i][j] = 0.f;

    for (int nc = 0; nc < NN / SPLITS; nc += 32) {
#pragma unroll
        for (int p = 0; p < 12; p++) {
            int idx = p * 256 + tid;
            int nn2 = idx & 31, d = idx >> 5;
            Qs[nn2][d] = qp[d * NN + n0 + nc + nn2];
            Ks[nn2][d] = kp[d * NN + n0 + nc + nn2];
        }
        __syncthreads();
#pragma unroll
        for (int kk = 0; kk < 32; kk++) {
            float fq[6], fk[6];
#pragma unroll
            for (int i = 0; i < 6; i++) fq[i] = Qs[kk][ty * 6 + i];
#pragma unroll
            for (int j = 0; j < 6; j++) fk[j] = Ks[kk][tx * 6 + j];
#pragma unroll
            for (int i = 0; i < 6; i++)
#pragma unroll
                for (int j = 0; j < 6; j++)
                    acc[i][j] = fmaf(fq[i], fk[j], acc[i][j]);
        }
        __syncthreads();
    }

    float* dst = g_part + ((size_t)blockIdx.y * BH + bh) * DD * DD;
#pragma unroll
    for (int i = 0; i < 6; i++)
#pragma unroll
        for (int j = 0; j < 6; j++)
            dst[(ty * 6 + i) * DD + tx * 6 + j] = acc[i][j];
}

// ---------------------------------------------------------------------------
// Kernel: reduce split-K partials, apply norms * temp, softmax over e.
// ---------------------------------------------------------------------------
__global__ __launch_bounds__(128) void softmax_kernel(const float* __restrict__ temp)
{
    const int bhd = blockIdx.x;
    const int bh = bhd / DD;
    const int d  = bhd - bh * DD;
    const int h  = bh & (HH - 1);
    const int e  = threadIdx.x;

    float raw = 0.f;
    float val = -1e30f;
    if (e < DD) {
        float s = 0.f;
#pragma unroll
        for (int sp = 0; sp < SPLITS; sp++)
            s += g_part[(((size_t)sp * BH + bh) * DD + d) * DD + e];
        raw = s * g_rq[bh * DD + d] * g_rk[bh * DD + e] * temp[h];
        val = raw;
    }

    __shared__ float red[128];
    red[e] = val;
    __syncthreads();
#pragma unroll
    for (int off = 64; off >= 1; off >>= 1) {
        if (e < off) red[e] = fmaxf(red[e], red[e + off]);
        __syncthreads();
    }
    float m = red[0];
    __syncthreads();

    float ex = (e < DD) ? expf(raw - m) : 0.f;
    red[e] = ex;
    __syncthreads();
#pragma unroll
    for (int off = 64; off >= 1; off >>= 1) {
        if (e < off) red[e] += red[e + off];
        __syncthreads();
    }
    float sum = red[0];

    if (e < DD)
        g_attn[((size_t)bh * DD + d) * DD + e] = ex / sum;
}

// ---------------------------------------------------------------------------
// Kernel: y_t[d][n] = sum_e attn[d][e] * v[e][n] (FFMA; small)
// ---------------------------------------------------------------------------
__global__ __launch_bounds__(256) void av_kernel()
{
    __shared__ float As_[96][33];
    __shared__ float Vs[32][128];
    const int tid = threadIdx.x;
    const int bh = blockIdx.x;
    const int n0 = blockIdx.y * 128;
    const float* ap = g_attn + (size_t)bh * DD * DD;
    const float* vp = g_v + (size_t)bh * DD * NN;
    const int tx = tid & 15;
    const int ty = tid >> 4;

    float acc[6][8];
#pragma unroll
    for (int i = 0; i < 6; i++)
#pragma unroll
        for (int j = 0; j < 8; j++) acc[i][j] = 0.f;

    for (int ec = 0; ec < DD; ec += 32) {
#pragma unroll
        for (int p = 0; p < 12; p++) {
            int idx = p * 256 + tid;
            int ee = idx & 31, d = idx >> 5;
            As_[d][ee] = ap[d * DD + ec + ee];
        }
#pragma unroll
        for (int p = 0; p < 16; p++) {
            int idx = p * 256 + tid;
            int nn2 = idx & 127, ee = idx >> 7;
            Vs[ee][nn2] = vp[(size_t)(ec + ee) * NN + n0 + nn2];
        }
        __syncthreads();
#pragma unroll
        for (int kk = 0; kk < 32; kk++) {
            float fa[6];
#pragma unroll
            for (int i = 0; i < 6; i++) fa[i] = As_[ty * 6 + i][kk];
            float4 v0 = *(const float4*)&Vs[kk][tx * 8];
            float4 v1 = *(const float4*)&Vs[kk][tx * 8 + 4];
            float fv[8] = {v0.x, v0.y, v0.z, v0.w, v1.x, v1.y, v1.z, v1.w};
#pragma unroll
            for (int i = 0; i < 6; i++)
#pragma unroll
                for (int j = 0; j < 8; j++)
                    acc[i][j] = fmaf(fa[i], fv[j], acc[i][j]);
        }
        __syncthreads();
    }

    float* yp = g_yt + (size_t)bh * DD * NN;
#pragma unroll
    for (int i = 0; i < 6; i++) {
        int d = ty * 6 + i;
        float4 o0 = {acc[i][0], acc[i][1], acc[i][2], acc[i][3]};
        float4 o1 = {acc[i][4], acc[i][5], acc[i][6], acc[i][7]};
        *(float4*)&yp[(size_t)d * NN + n0 + tx * 8]     = o0;
        *(float4*)&yp[(size_t)d * NN + n0 + tx * 8 + 4] = o1;
    }
}

// ---------------------------------------------------------------------------
extern "C" void kernel_launch(void* const* d_in, const int* in_sizes, int n_in,
                              void* d_out, int out_size)
{
    const float* x      = (const float*)d_in[0];
    const float* w_qkv  = (const float*)d_in[1];
    const float* w_proj = (const float*)d_in[2];
    const float* b_proj = (const float*)d_in[3];
    const float* temp   = (const float*)d_in[4];
    float* out = (float*)d_out;

    split_x_kernel<<<(BB * NN * CC / 4) / 256, 256>>>(x);
    split_wqkv_kernel<<<(CC * C3 / 4) / 256, 256>>>(w_qkv);
    split_wproj_kernel<<<(CC * CC / 4) / 256, 256>>>(w_proj);

    // GEMM1: [32768 x 2304(bf16 split K)] x [2304 x 2304] -> scatter q/k/v
    mma_gemm_kernel<<<dim3(C3 / 128, (BB * NN) / 128), 256>>>(C3, 0, nullptr, nullptr);

    norm_kernel<<<dim3(BH * DD, 2), 256>>>();
    attn_part_kernel<<<dim3(BH, SPLITS), 256>>>();
    softmax_kernel<<<BH * DD, 128>>>(temp);
    av_kernel<<<dim3(BH, NN / 128), 256>>>();

    ysplit_kernel<<<dim3(NN / 32, CC / 32, BB), dim3(32, 8)>>>();

    // GEMM2: [32768 x 2304] x [2304 x 768] -> out + bias
    mma_gemm_kernel<<<dim3(CC / 128, (BB * NN) / 128), 256>>>(CC, 1, b_proj, out);
}

// round 5
// speedup vs baseline: 2.7445x; 1.2872x over previous
#include <cuda_runtime.h>
#include <cuda_fp16.h>
#include <math.h>

// Problem constants
#define BB 8
#define NN 4096
#define CC 768
#define HH 8
#define DD 96
#define C3 2304
#define BH (BB*HH)
#define SPLITS 8
#define K3 1536   // 2*CC: fp16 split-K depth (A=[hi|lo], B=[hi;hi])

// Scratch (device globals — allocation-free kernel_launch)
__device__ float g_q[BB*HH*DD*NN];     // [b][h][d][n]
__device__ float g_k[BB*HH*DD*NN];
__device__ float g_v[BB*HH*DD*NN];
__device__ float g_rq[BB*HH*DD];
__device__ float g_rk[BB*HH*DD];
__device__ float g_part[SPLITS*BH*DD*DD];
__device__ float g_attn[BH*DD*DD];
__device__ float g_yt[BB*HH*DD*NN];    // y transposed: [b][h][d][n]

// fp16 split operands
__device__ __half g_xs[(size_t)BB*NN*K3];   // A' GEMM1: [32768][1536] = [hi|lo]
__device__ __half g_ws[(size_t)K3*C3];      // B' GEMM1: [1536][2304] = [hi;hi]
__device__ __half g_ys[(size_t)BB*NN*K3];   // A' GEMM2
__device__ __half g_wps[(size_t)K3*CC];     // B' GEMM2

// ---------------------------------------------------------------------------
// MMA / ldmatrix helpers
// ---------------------------------------------------------------------------
__device__ __forceinline__ void mma16816(float* c, const unsigned* a, const unsigned* b) {
    asm volatile(
        "mma.sync.aligned.m16n8k16.row.col.f32.f16.f16.f32 "
        "{%0,%1,%2,%3}, {%4,%5,%6,%7}, {%8,%9}, {%0,%1,%2,%3};"
        : "+f"(c[0]), "+f"(c[1]), "+f"(c[2]), "+f"(c[3])
        : "r"(a[0]), "r"(a[1]), "r"(a[2]), "r"(a[3]), "r"(b[0]), "r"(b[1]));
}
__device__ __forceinline__ void ldsm_x4(unsigned* r, const void* p) {
    unsigned addr = (unsigned)__cvta_generic_to_shared(p);
    asm volatile("ldmatrix.sync.aligned.m8n8.x4.shared.b16 {%0,%1,%2,%3}, [%4];"
        : "=r"(r[0]), "=r"(r[1]), "=r"(r[2]), "=r"(r[3]) : "r"(addr));
}
__device__ __forceinline__ void ldsm_x4_t(unsigned* r, const void* p) {
    unsigned addr = (unsigned)__cvta_generic_to_shared(p);
    asm volatile("ldmatrix.sync.aligned.m8n8.x4.trans.shared.b16 {%0,%1,%2,%3}, [%4];"
        : "=r"(r[0]), "=r"(r[1]), "=r"(r[2]), "=r"(r[3]) : "r"(addr));
}
__device__ __forceinline__ void split_hl(float v, __half& hi, __half& lo) {
    hi = __float2half(v);
    lo = __float2half(v - __half2float(hi));
}

// ---------------------------------------------------------------------------
// Split kernels: fp32 -> fp16 blocks along K
// A-side: [hi | lo]; B-side: [hi ; hi]  (B's lo term dropped; err ~2^-11)
// ---------------------------------------------------------------------------
__global__ __launch_bounds__(256) void split_x_kernel(const float* __restrict__ x)
{
    int idx = blockIdx.x * 256 + threadIdx.x;        // one float4 per thread
    int m = idx / (CC / 4);
    int k4 = (idx - m * (CC / 4)) * 4;
    float4 v = *(const float4*)&x[(size_t)m * CC + k4];
    __half hi[4], lo[4];
    split_hl(v.x, hi[0], lo[0]); split_hl(v.y, hi[1], lo[1]);
    split_hl(v.z, hi[2], lo[2]); split_hl(v.w, hi[3], lo[3]);
    __half* base = g_xs + (size_t)m * K3 + k4;
    *(uint2*)(base)      = *(uint2*)hi;
    *(uint2*)(base + CC) = *(uint2*)lo;
}

__global__ __launch_bounds__(256) void split_wqkv_kernel(const float* __restrict__ w)
{
    int idx = blockIdx.x * 256 + threadIdx.x;
    int k = idx / (C3 / 4);
    int n4 = (idx - k * (C3 / 4)) * 4;
    float4 v = *(const float4*)&w[(size_t)k * C3 + n4];
    __half hi[4];
    hi[0] = __float2half(v.x); hi[1] = __float2half(v.y);
    hi[2] = __float2half(v.z); hi[3] = __float2half(v.w);
    *(uint2*)&g_ws[(size_t)k * C3 + n4]        = *(uint2*)hi;
    *(uint2*)&g_ws[(size_t)(k + CC) * C3 + n4] = *(uint2*)hi;
}

__global__ __launch_bounds__(256) void split_wproj_kernel(const float* __restrict__ w)
{
    int idx = blockIdx.x * 256 + threadIdx.x;
    int k = idx / (CC / 4);
    int n4 = (idx - k * (CC / 4)) * 4;
    float4 v = *(const float4*)&w[(size_t)k * CC + n4];
    __half hi[4];
    hi[0] = __float2half(v.x); hi[1] = __float2half(v.y);
    hi[2] = __float2half(v.z); hi[3] = __float2half(v.w);
    *(uint2*)&g_wps[(size_t)k * CC + n4]        = *(uint2*)hi;
    *(uint2*)&g_wps[(size_t)(k + CC) * CC + n4] = *(uint2*)hi;
}

// Transpose g_yt [b][c][n] f32 -> g_ys [b*N+n][hi|lo over c] fp16
__global__ __launch_bounds__(256) void ysplit_kernel()
{
    __shared__ float sm[32][33];
    const int n0 = blockIdx.x * 32;
    const int c0 = blockIdx.y * 32;
    const int b  = blockIdx.z;
    const int tx = threadIdx.x, ty = threadIdx.y;   // 32 x 8
#pragma unroll
    for (int i = 0; i < 4; i++) {
        int c = c0 + ty + i * 8;
        sm[ty + i * 8][tx] = g_yt[((size_t)b * CC + c) * NN + n0 + tx];
    }
    __syncthreads();
#pragma unroll
    for (int i = 0; i < 4; i++) {
        int n = n0 + ty + i * 8;
        int c = c0 + tx;
        __half hi, lo;
        split_hl(sm[tx][ty + i * 8], hi, lo);
        __half* base = g_ys + ((size_t)b * NN + n) * K3;
        base[c]      = hi;
        base[CC + c] = lo;
    }
}

// ---------------------------------------------------------------------------
// fp16 MMA GEMM: C[M x Ncols] = A'[M x 1536] * B'[1536 x Ncols]  (fp32 accum)
// BM=128, BN=128, BK=32, 256 threads = 8 warps (4m x 2n), warp tile 32x64.
// mode 0: scatter GEMM1 output into g_q/g_k/g_v.  mode 1: out = C + bias.
// ---------------------------------------------------------------------------
__global__ __launch_bounds__(256) void mma_gemm_kernel(
    int Ncols, int mode, const float* __restrict__ bias, float* __restrict__ out)
{
    __shared__ __align__(16) __half As[128][40];   // pad 32->40: ldsm conflict-free
    __shared__ __align__(16) __half Bs[32][136];   // pad 128->136
    const __half* __restrict__ A  = mode ? g_ys  : g_xs;
    const __half* __restrict__ Bm = mode ? g_wps : g_ws;

    const int tid = threadIdx.x;
    const int wid = tid >> 5, lane = tid & 31;
    const int rowBase = blockIdx.y * 128;
    const int colBase = blockIdx.x * 128;
    const int warpM = (wid & 3) * 32;
    const int warpN = (wid >> 2) * 64;

    float acc[2][8][4];
#pragma unroll
    for (int i = 0; i < 2; i++)
#pragma unroll
        for (int j = 0; j < 8; j++)
#pragma unroll
            for (int q = 0; q < 4; q++) acc[i][j][q] = 0.f;

    const int arow = tid >> 2, acol = (tid & 3) * 8;
    const int brow = tid >> 4, bcol = (tid & 15) * 8;

    for (int t = 0; t < K3 / 32; t++) {
        const int k0 = t * 32;
        uint4 a0 = *(const uint4*)&A[(size_t)(rowBase + arow) * K3 + k0 + acol];
        uint4 a1 = *(const uint4*)&A[(size_t)(rowBase + arow + 64) * K3 + k0 + acol];
        uint4 b0 = *(const uint4*)&Bm[(size_t)(k0 + brow) * Ncols + colBase + bcol];
        uint4 b1 = *(const uint4*)&Bm[(size_t)(k0 + brow + 16) * Ncols + colBase + bcol];

        if (t) __syncthreads();
        *(uint4*)&As[arow][acol]      = a0;
        *(uint4*)&As[arow + 64][acol] = a1;
        *(uint4*)&Bs[brow][bcol]      = b0;
        *(uint4*)&Bs[brow + 16][bcol] = b1;
        __syncthreads();

#pragma unroll
        for (int ks = 0; ks < 2; ks++) {
            unsigned af[2][4];
#pragma unroll
            for (int im = 0; im < 2; im++)
                ldsm_x4(af[im], &As[warpM + im * 16 + (lane & 15)]
                                   [ks * 16 + (lane >> 4) * 8]);
            unsigned bf[8][2];
#pragma unroll
            for (int g = 0; g < 4; g++) {
                unsigned r[4];
                ldsm_x4_t(r, &Bs[ks * 16 + ((lane >> 3) & 1) * 8 + (lane & 7)]
                             [warpN + g * 16 + (lane >> 4) * 8]);
                bf[2 * g][0] = r[0]; bf[2 * g][1] = r[1];
                bf[2 * g + 1][0] = r[2]; bf[2 * g + 1][1] = r[3];
            }
#pragma unroll
            for (int im = 0; im < 2; im++)
#pragma unroll
                for (int jn = 0; jn < 8; jn++)
                    mma16816(acc[im][jn], af[im], bf[jn]);
        }
    }

    // Epilogue
#pragma unroll
    for (int im = 0; im < 2; im++) {
#pragma unroll
        for (int jn = 0; jn < 8; jn++) {
#pragma unroll
            for (int q = 0; q < 4; q++) {
                int m = warpM + im * 16 + (lane >> 2) + (q >> 1) * 8;
                int n = warpN + jn * 8 + (lane & 3) * 2 + (q & 1);
                float val = acc[im][jn][q];
                int row = rowBase + m;
                int col = colBase + n;
                if (mode == 0) {
                    int b = row >> 12;
                    int nn2 = row & 4095;
                    int h = col / 288;
                    int rem = col - h * 288;
                    int d = rem / 3;
                    int s = rem - d * 3;
                    float* dst = (s == 0) ? g_q : (s == 1) ? g_k : g_v;
                    dst[((b * HH + h) * DD + d) * NN + nn2] = val;
                } else {
                    out[(size_t)row * CC + col] = val + bias[col];
                }
            }
        }
    }
}

// ---------------------------------------------------------------------------
// Kernel: per-(b,h,d) inverse L2 norm over N for q (y=0) and k (y=1)
// ---------------------------------------------------------------------------
__global__ __launch_bounds__(256) void norm_kernel()
{
    const int row = blockIdx.x;
    const float* src = (blockIdx.y == 0) ? g_q : g_k;
    float*       dst = (blockIdx.y == 0) ? g_rq : g_rk;
    const float* p = src + (size_t)row * NN;
    float s = 0.f;
    for (int i = threadIdx.x; i < NN; i += 256) {
        float v = p[i];
        s = fmaf(v, v, s);
    }
#pragma unroll
    for (int off = 16; off; off >>= 1) s += __shfl_down_sync(0xffffffffu, s, off);
    __shared__ float ws[8];
    if ((threadIdx.x & 31) == 0) ws[threadIdx.x >> 5] = s;
    __syncthreads();
    if (threadIdx.x < 8) {
        float t = ws[threadIdx.x];
#pragma unroll
        for (int off = 4; off; off >>= 1) t += __shfl_down_sync(0xffu, t, off);
        if (threadIdx.x == 0) dst[row] = rsqrtf(t);
    }
}

// ---------------------------------------------------------------------------
// Kernel: cross-covariance partials (FFMA; small)
// ---------------------------------------------------------------------------
__global__ __launch_bounds__(256) void attn_part_kernel()
{
    __shared__ float Qs[32][97];
    __shared__ float Ks[32][97];
    const int tid = threadIdx.x;
    const int bh = blockIdx.x;
    const int n0 = blockIdx.y * (NN / SPLITS);
    const float* qp = g_q + (size_t)bh * DD * NN;
    const float* kp = g_k + (size_t)bh * DD * NN;
    const int tx = tid & 15;
    const int ty = tid >> 4;

    float acc[6][6];
#pragma unroll
    for (int i = 0; i < 6; i++)
#pragma unroll
        for (int j = 0; j < 6; j++) acc[i][j] = 0.f;

    for (int nc = 0; nc < NN / SPLITS; nc += 32) {
#pragma unroll
        for (int p = 0; p < 12; p++) {
            int idx = p * 256 + tid;
            int nn2 = idx & 31, d = idx >> 5;
            Qs[nn2][d] = qp[d * NN + n0 + nc + nn2];
            Ks[nn2][d] = kp[d * NN + n0 + nc + nn2];
        }
        __syncthreads();
#pragma unroll
        for (int kk = 0; kk < 32; kk++) {
            float fq[6], fk[6];
#pragma unroll
            for (int i = 0; i < 6; i++) fq[i] = Qs[kk][ty * 6 + i];
#pragma unroll
            for (int j = 0; j < 6; j++) fk[j] = Ks[kk][tx * 6 + j];
#pragma unroll
            for (int i = 0; i < 6; i++)
#pragma unroll
                for (int j = 0; j < 6; j++)
                    acc[i][j] = fmaf(fq[i], fk[j], acc[i][j]);
        }
        __syncthreads();
    }

    float* dst = g_part + ((size_t)blockIdx.y * BH + bh) * DD * DD;
#pragma unroll
    for (int i = 0; i < 6; i++)
#pragma unroll
        for (int j = 0; j < 6; j++)
            dst[(ty * 6 + i) * DD + tx * 6 + j] = acc[i][j];
}

// ---------------------------------------------------------------------------
// Kernel: reduce split-K partials, apply norms * temp, softmax over e.
// ---------------------------------------------------------------------------
__global__ __launch_bounds__(128) void softmax_kernel(const float* __restrict__ temp)
{
    const int bhd = blockIdx.x;
    const int bh = bhd / DD;
    const int d  = bhd - bh * DD;
    const int h  = bh & (HH - 1);
    const int e  = threadIdx.x;

    float raw = 0.f;
    float val = -1e30f;
    if (e < DD) {
        float s = 0.f;
#pragma unroll
        for (int sp = 0; sp < SPLITS; sp++)
            s += g_part[(((size_t)sp * BH + bh) * DD + d) * DD + e];
        raw = s * g_rq[bh * DD + d] * g_rk[bh * DD + e] * temp[h];
        val = raw;
    }

    __shared__ float red[128];
    red[e] = val;
    __syncthreads();
#pragma unroll
    for (int off = 64; off >= 1; off >>= 1) {
        if (e < off) red[e] = fmaxf(red[e], red[e + off]);
        __syncthreads();
    }
    float m = red[0];
    __syncthreads();

    float ex = (e < DD) ? expf(raw - m) : 0.f;
    red[e] = ex;
    __syncthreads();
#pragma unroll
    for (int off = 64; off >= 1; off >>= 1) {
        if (e < off) red[e] += red[e + off];
        __syncthreads();
    }
    float sum = red[0];

    if (e < DD)
        g_attn[((size_t)bh * DD + d) * DD + e] = ex / sum;
}

// ---------------------------------------------------------------------------
// Kernel: y_t[d][n] = sum_e attn[d][e] * v[e][n] (FFMA; small)
// ---------------------------------------------------------------------------
__global__ __launch_bounds__(256) void av_kernel()
{
    __shared__ float As_[96][33];
    __shared__ float Vs[32][128];
    const int tid = threadIdx.x;
    const int bh = blockIdx.x;
    const int n0 = blockIdx.y * 128;
    const float* ap = g_attn + (size_t)bh * DD * DD;
    const float* vp = g_v + (size_t)bh * DD * NN;
    const int tx = tid & 15;
    const int ty = tid >> 4;

    float acc[6][8];
#pragma unroll
    for (int i = 0; i < 6; i++)
#pragma unroll
        for (int j = 0; j < 8; j++) acc[i][j] = 0.f;

    for (int ec = 0; ec < DD; ec += 32) {
#pragma unroll
        for (int p = 0; p < 12; p++) {
            int idx = p * 256 + tid;
            int ee = idx & 31, d = idx >> 5;
            As_[d][ee] = ap[d * DD + ec + ee];
        }
#pragma unroll
        for (int p = 0; p < 16; p++) {
            int idx = p * 256 + tid;
            int nn2 = idx & 127, ee = idx >> 7;
            Vs[ee][nn2] = vp[(size_t)(ec + ee) * NN + n0 + nn2];
        }
        __syncthreads();
#pragma unroll
        for (int kk = 0; kk < 32; kk++) {
            float fa[6];
#pragma unroll
            for (int i = 0; i < 6; i++) fa[i] = As_[ty * 6 + i][kk];
            float4 v0 = *(const float4*)&Vs[kk][tx * 8];
            float4 v1 = *(const float4*)&Vs[kk][tx * 8 + 4];
            float fv[8] = {v0.x, v0.y, v0.z, v0.w, v1.x, v1.y, v1.z, v1.w};
#pragma unroll
            for (int i = 0; i < 6; i++)
#pragma unroll
                for (int j = 0; j < 8; j++)
                    acc[i][j] = fmaf(fa[i], fv[j], acc[i][j]);
        }
        __syncthreads();
    }

    float* yp = g_yt + (size_t)bh * DD * NN;
#pragma unroll
    for (int i = 0; i < 6; i++) {
        int d = ty * 6 + i;
        float4 o0 = {acc[i][0], acc[i][1], acc[i][2], acc[i][3]};
        float4 o1 = {acc[i][4], acc[i][5], acc[i][6], acc[i][7]};
        *(float4*)&yp[(size_t)d * NN + n0 + tx * 8]     = o0;
        *(float4*)&yp[(size_t)d * NN + n0 + tx * 8 + 4] = o1;
    }
}

// ---------------------------------------------------------------------------
extern "C" void kernel_launch(void* const* d_in, const int* in_sizes, int n_in,
                              void* d_out, int out_size)
{
    const float* x      = (const float*)d_in[0];
    const float* w_qkv  = (const float*)d_in[1];
    const float* w_proj = (const float*)d_in[2];
    const float* b_proj = (const float*)d_in[3];
    const float* temp   = (const float*)d_in[4];
    float* out = (float*)d_out;

    split_x_kernel<<<(BB * NN * CC / 4) / 256, 256>>>(x);
    split_wqkv_kernel<<<(CC * C3 / 4) / 256, 256>>>(w_qkv);
    split_wproj_kernel<<<(CC * CC / 4) / 256, 256>>>(w_proj);

    // GEMM1: [32768 x 1536(fp16 split K)] x [1536 x 2304] -> scatter q/k/v
    mma_gemm_kernel<<<dim3(C3 / 128, (BB * NN) / 128), 256>>>(C3, 0, nullptr, nullptr);

    norm_kernel<<<dim3(BH * DD, 2), 256>>>();
    attn_part_kernel<<<dim3(BH, SPLITS), 256>>>();
    softmax_kernel<<<BH * DD, 128>>>(temp);
    av_kernel<<<dim3(BH, NN / 128), 256>>>();

    ysplit_kernel<<<dim3(NN / 32, CC / 32, BB), dim3(32, 8)>>>();

    // GEMM2: [32768 x 1536] x [1536 x 768] -> out + bias
    mma_gemm_kernel<<<dim3(CC / 128, (BB * NN) / 128), 256>>>(CC, 1, b_proj, out);
}